// round 17
// baseline (speedup 1.0000x reference)
#include <cuda_runtime.h>
#include <cuda_fp16.h>
#include <math.h>
#include <stdint.h>

// ---------------- problem constants ----------------
#define B_ 256
#define S_ 14
#define C_ 2513
#define SB 3584          // S_*B_
#define BH 262144        // B_*H_
#define G4 4096          // 4*H_
#define CLS_NB 20        // ceil(2513/128)
#define WC_ROWS 2560     // padded classifier rows
#define PROJ_TILES 1792
#define PRELAUNCH 608
#define RIDE 88

// ---------------- fp16 mma GEMM config (128x128, 256 thr, occ 2) ----------
// Tiled operand layout: block (mb, kc) = 8KB contiguous [row 128][k 32].
#define STAGE_H   4096                  // halves per operand per stage
#define SLOT_H    (2 * STAGE_H)         // A+B per stage
#define NSTAGE    4
#define MBAR_OFF  0                     // 4 mbarriers (32 B)
#define SLOTS_OFF 64                    // halves; 128 B aligned
#define MAIN_H    (NSTAGE * SLOT_H)     // 32768 halves
#define EPI_OFF   (SLOTS_OFF + MAIN_H)
#define SMEM_LSTM ((EPI_OFF + 4096) * 2)   // + h tile 8KB = 73856 B
#define SMEM_LIN  ((EPI_OFF + 256) * 2)    // + bias row    = 66176 B

// ---------------- scratch (device globals; all fp16 operands TILED) --------
__device__ __half g_xT [SB * 1024];
__device__ float  g_xg_r[(size_t)SB * G4];
__device__ float  g_xg_u[(size_t)SB * G4];
__device__ __half g_hu [2 * SB * 1024];
__device__ float  g_cu [SB * 1024];
__device__ __half g_hn [SB * 1024];
__device__ __half g_whhr[(size_t)G4 * 1024];
__device__ __half g_wihr[(size_t)G4 * 1024];
__device__ __half g_wihu[(size_t)G4 * 1024];
__device__ __half g_whhu[(size_t)G4 * 1024];
__device__ __half g_wc [(size_t)WC_ROWS * 1024];

__device__ __forceinline__ float sigf(float x) { return 1.0f / (1.0f + expf(-x)); }

// logical-k permutation within each 32-k block
__device__ __forceinline__ int perm_l(int p) {
    int b = (p >> 2) & 1, t = p >> 3, j = p & 3;
    return b * 16 + ((j < 2) ? (2 * t + j) : (2 * t + 8 + (j - 2)));
}
__device__ __forceinline__ int inv_l(int l) {
    int b = l >> 4, r = l & 15, hi = r >> 3, t = (r >> 1) & 3, e = r & 1;
    return t * 8 + b * 4 + hi * 2 + e;
}

// ---------------- low-level helpers ----------------
__device__ __forceinline__ uint32_t smaddr(const void* p) {
    uint32_t a;
    asm("{ .reg .u64 t; cvta.to.shared.u64 t, %1; cvt.u32.u64 %0, t; }" : "=r"(a) : "l"(p));
    return a;
}
#define MBARRIER_INIT(mb, cnt) \
    asm volatile("mbarrier.init.shared.b64 [%0], %1;" :: "r"((uint32_t)(mb)), "r"((uint32_t)(cnt)) : "memory")
#define MBARRIER_WAIT_PARITY(mb, par) do { \
    uint32_t _m = (uint32_t)(mb); uint32_t _p = (uint32_t)(par); uint32_t _d; \
    asm volatile("{\n\t.reg .pred p;\n\tmbarrier.try_wait.parity.acquire.cta.shared::cta.b64 p, [%1], %2;\n\tselp.b32 %0,1,0,p;\n\t}" \
        : "=r"(_d) : "r"(_m), "r"(_p) : "memory"); \
    if (!_d) { \
        asm volatile("{\n\t.reg .pred P1;\n\tWL_%=:\n\tmbarrier.try_wait.parity.acquire.cta.shared::cta.b64 P1, [%0], %1, 0x989680;\n\t@P1 bra.uni WD_%=;\n\tbra.uni WL_%=;\n\tWD_%=:\n\t}" \
            :: "r"(_m), "r"(_p) : "memory"); \
    } } while (0)

__device__ __forceinline__ void bulk_issue(uint32_t mbar, uint32_t dst,
                                           const __half* srcA, const __half* srcB) {
    asm volatile("mbarrier.arrive.expect_tx.shared.b64 _, [%0], %1;"
                 :: "r"(mbar), "r"(16384u) : "memory");
    asm volatile("cp.async.bulk.shared::cta.global.mbarrier::complete_tx::bytes [%0], [%1], %2, [%3];"
                 :: "r"(dst), "l"(srcA), "r"(8192u), "r"(mbar) : "memory");
    asm volatile("cp.async.bulk.shared::cta.global.mbarrier::complete_tx::bytes [%0], [%1], %2, [%3];"
                 :: "r"(dst + STAGE_H * 2), "l"(srcB), "r"(8192u), "r"(mbar) : "memory");
}
__device__ __forceinline__ void mma16(float* d, const uint32_t* a, const uint32_t* b) {
    asm volatile(
        "mma.sync.aligned.m16n8k16.row.col.f32.f16.f16.f32 "
        "{%0,%1,%2,%3},{%4,%5,%6,%7},{%8,%9},{%0,%1,%2,%3};"
        : "+f"(d[0]), "+f"(d[1]), "+f"(d[2]), "+f"(d[3])
        : "r"(a[0]), "r"(a[1]), "r"(a[2]), "r"(a[3]), "r"(b[0]), "r"(b[1]));
}

// ---------------- stage compute: 64x32 warp tile, 32 MMAs ------------------
__device__ __forceinline__ void stage_compute(
    const __half* slots, int slot, int wm, int wn, int g, int tig, float acc[4][4][4])
{
    const __half* bA = slots + slot * SLOT_H + (size_t)(wm * 64 + g) * 32 + tig * 8;
    const __half* bB = slots + slot * SLOT_H + STAGE_H + (size_t)(wn * 32 + g) * 32 + tig * 8;
    uint4 bq[4];
#pragma unroll
    for (int ni = 0; ni < 4; ni++)
        bq[ni] = *(const uint4*)(bB + ni * 8 * 32);
#pragma unroll
    for (int mp = 0; mp < 2; mp++) {
        const int m0i = mp * 2, m1i = mp * 2 + 1;
        uint4 alo0 = *(const uint4*)(bA + m0i * 16 * 32);
        uint4 ahi0 = *(const uint4*)(bA + (m0i * 16 + 8) * 32);
        uint4 alo1 = *(const uint4*)(bA + m1i * 16 * 32);
        uint4 ahi1 = *(const uint4*)(bA + (m1i * 16 + 8) * 32);
        uint32_t a00[4] = {alo0.x, ahi0.x, alo0.y, ahi0.y};
        uint32_t a01[4] = {alo0.z, ahi0.z, alo0.w, ahi0.w};
        uint32_t a10[4] = {alo1.x, ahi1.x, alo1.y, ahi1.y};
        uint32_t a11[4] = {alo1.z, ahi1.z, alo1.w, ahi1.w};
#pragma unroll
        for (int ni = 0; ni < 4; ni++) {
            uint32_t bf0[2] = {bq[ni].x, bq[ni].y};
            mma16(acc[m0i][ni], a00, bf0);
        }
#pragma unroll
        for (int ni = 0; ni < 4; ni++) {
            uint32_t bf0[2] = {bq[ni].x, bq[ni].y};
            mma16(acc[m1i][ni], a10, bf0);
        }
#pragma unroll
        for (int ni = 0; ni < 4; ni++) {
            uint32_t bf1[2] = {bq[ni].z, bq[ni].w};
            mma16(acc[m0i][ni], a01, bf1);
        }
#pragma unroll
        for (int ni = 0; ni < 4; ni++) {
            uint32_t bf1[2] = {bq[ni].z, bq[ni].w};
            mma16(acc[m1i][ni], a11, bf1);
        }
    }
}

// ---------------- bulk-copy K=1024 mainloop (4-stage mbarrier ring) --------
// Ablk/Bblk point to the tile's k-chunk-0 8KB block; chunk stride 4096 halves.
__device__ __forceinline__ void run_mainloop(
    __half* smh, const __half* __restrict__ Ablk, const __half* __restrict__ Bblk,
    float acc[4][4][4], int tid, int wm, int wn, int g, int tig)
{
    uint32_t mb = smaddr(smh + MBAR_OFF);
    uint32_t sb = smaddr(smh + SLOTS_OFF);
    __half* slots = smh + SLOTS_OFF;
    if (tid == 0) {
#pragma unroll
        for (int s = 0; s < 4; s++) MBARRIER_INIT(mb + s * 8, 1);
    }
    __syncthreads();
    if (tid == 0) {
#pragma unroll
        for (int s = 0; s < 3; s++)
            bulk_issue(mb + s * 8, sb + s * SLOT_H * 2, Ablk + s * 4096, Bblk + s * 4096);
    }
#pragma unroll 1
    for (int kt = 0; kt < 32; kt++) {
        int s = kt & 3;
        MBARRIER_WAIT_PARITY(mb + s * 8, (kt >> 2) & 1);
        __syncthreads();
        if (tid == 0 && kt + 3 < 32) {
            int s2 = (kt + 3) & 3;
            bulk_issue(mb + s2 * 8, sb + s2 * SLOT_H * 2,
                       Ablk + (kt + 3) * 4096, Bblk + (kt + 3) * 4096);
        }
        stage_compute(slots, s, wm, wn, g, tig, acc);
    }
}

// ---------------- projection tile (device fn) ------------------------------
__device__ __forceinline__ void proj_tile(
    __half* smh, const __half* __restrict__ A, const __half* __restrict__ W,
    float* __restrict__ Out, const float* __restrict__ b0,
    const float* __restrict__ b1, int m0, int n0,
    int tid, int wm, int wn, int g, int tig)
{
    float* biasS = (float*)(smh + EPI_OFF);
    if (tid < 128) {
        int np = n0 + tid;
        int wr = ((np & 3) << 10) | (np >> 2);
        biasS[tid] = b0[wr] + b1[wr];
    }
    float acc[4][4][4];
#pragma unroll
    for (int a = 0; a < 4; a++)
#pragma unroll
        for (int b = 0; b < 4; b++)
#pragma unroll
            for (int c = 0; c < 4; c++) acc[a][b][c] = 0.f;

    run_mainloop(smh, A + (size_t)(m0 >> 7) * 32 * 4096,
                 W + (size_t)(n0 >> 7) * 32 * 4096, acc, tid, wm, wn, g, tig);

#pragma unroll
    for (int mi = 0; mi < 4; mi++) {
        const int R0 = m0 + wm * 64 + mi * 16;
#pragma unroll
        for (int ni = 0; ni < 4; ni++) {
            const int v = n0 + wn * 32 + ni * 8 + 2 * tig;
            const float bA0 = biasS[v - n0], bA1 = biasS[v - n0 + 1];
            const int r1 = R0 + g, r2 = R0 + g + 8;
            float2 s1 = make_float2(acc[mi][ni][0] + bA0, acc[mi][ni][1] + bA1);
            float2 s2 = make_float2(acc[mi][ni][2] + bA0, acc[mi][ni][3] + bA1);
            *(float2*)(Out + (size_t)r1 * G4 + v) = s1;
            *(float2*)(Out + (size_t)r2 * G4 + v) = s2;
        }
    }
}

// ---------------- proj queue decode ----------------------------------------
__device__ __forceinline__ void projq_tile(
    __half* smh, int q,
    const __half* __restrict__ xT,
    const __half* __restrict__ wihr, const __half* __restrict__ wihu,
    float* __restrict__ xg_r, float* __restrict__ xg_u,
    const float* __restrict__ bihr, const float* __restrict__ bhhr,
    const float* __restrict__ bihu, const float* __restrict__ bhhu,
    int tid, int wm, int wn, int g, int tig)
{
    if (q >= PROJ_TILES) return;
    const __half* W; float* O; const float *b0, *b1; int m0, n0;
    if (q < 896) {
        int slice = q >> 6, w = q & 63;
        m0 = (slice * 2 + (w >> 5)) * 128;
        n0 = (w & 31) * 128;
        W = wihr; O = xg_r; b0 = bihr; b1 = bhhr;
    } else {
        int p = q - 896;
        m0 = (p >> 5) * 128;
        n0 = (p & 31) * 128;
        W = wihu; O = xg_u; b0 = bihu; b1 = bhhu;
    }
    proj_tile(smh, xT, W, O, b0, b1, m0, n0, tid, wm, wn, g, tig);
}

__global__ void __launch_bounds__(256, 2) k_projq(
    const __half* __restrict__ xT,
    const __half* __restrict__ wihr, const __half* __restrict__ wihu,
    float* __restrict__ xg_r, float* __restrict__ xg_u,
    const float* __restrict__ bihr, const float* __restrict__ bhhr,
    const float* __restrict__ bihu, const float* __restrict__ bhhu)
{
    extern __shared__ __half smh[];
    const int tid = threadIdx.x, lane = tid & 31, wid = tid >> 5;
    const int wm = wid & 1, wn = wid >> 1, g = lane >> 2, tig = lane & 3;
    projq_tile(smh, blockIdx.x, xT, wihr, wihu, xg_r, xg_u,
               bihr, bhhr, bihu, bhhu, tid, wm, wn, g, tig);
}

// ---------------- LSTM epilogue (shared) ------------------------------------
__device__ __forceinline__ void lstm_epilogue(
    float acc[4][4][4], __half* smh, const float* __restrict__ xg,
    const float* __restrict__ Cin, float* __restrict__ Cout,
    __half* __restrict__ Hout, __half* __restrict__ hn,
    int m0, int n0, int final_t, int zeroInit,
    int tid, int wm, int wn, int g, int tig)
{
    __half* hsm = smh + EPI_OFF;
#pragma unroll
    for (int mi = 0; mi < 4; mi++) {
        const int R0 = m0 + wm * 64 + mi * 16;
#pragma unroll
        for (int ni = 0; ni < 4; ni++) {
            const int V0 = n0 + wn * 32 + ni * 8;
            float c0 = acc[mi][ni][0], c1 = acc[mi][ni][1];
            float c2 = acc[mi][ni][2], c3 = acc[mi][ni][3];
            int p = tig & 1;
            float x = p ? c0 : c2, y = p ? c1 : c3;
            float sx = __shfl_xor_sync(0xffffffffu, x, 1);
            float sy = __shfl_xor_sync(0xffffffffu, y, 1);
            float pi, pf, pg, po; int row;
            if (!p) { pi = c0; pf = c1; pg = sx; po = sy; row = R0 + g; }
            else    { pi = sx; pf = sy; pg = c2; po = c3; row = R0 + g + 8; }
            int u = (V0 >> 2) + (tig >> 1);
            float4 xv = *(const float4*)(xg + (size_t)row * G4 + u * 4);
            float ci = zeroInit ? 0.f : Cin[(size_t)row * 1024 + u];
            float cn = sigf(pf + xv.y) * ci + sigf(pi + xv.x) * tanhf(pg + xv.z);
            float hv = sigf(po + xv.w) * tanhf(cn);
            Cout[(size_t)row * 1024 + u] = cn;
            int ul = u - (n0 >> 2);
            hsm[(row - m0) * 32 + inv_l(ul)] = __float2half_rn(hv);
        }
    }
    __syncthreads();
    // contiguous 8KB block store (tiled layout)
    {
        int blk = (m0 >> 7) * 32 + (n0 >> 7);
        const uint4* src4 = (const uint4*)hsm;
        uint4 a = src4[tid], b = src4[tid + 256];
        uint4* gd = (uint4*)(Hout + (size_t)blk * 4096);
        gd[tid] = a; gd[tid + 256] = b;
        if ((m0 >> 8) == final_t) {
            uint4* fd = (uint4*)(hn + (size_t)blk * 4096);
            fd[tid] = a; fd[tid + 256] = b;
        }
    }
}

// ---------------- rolling step kernel (64 LSTM tiles + proj riders) --------
__global__ void __launch_bounds__(256, 2) k_roll(
    const __half* __restrict__ Hin, const __half* __restrict__ Whh,
    const float* __restrict__ xg,
    const float* __restrict__ Cin, float* __restrict__ Cout,
    __half* __restrict__ Hout, int zeroInit, int projBase,
    const __half* __restrict__ xT,
    const __half* __restrict__ wihr, const __half* __restrict__ wihu,
    float* __restrict__ xg_r, float* __restrict__ xg_u,
    const float* __restrict__ bihr, const float* __restrict__ bhhr,
    const float* __restrict__ bihu, const float* __restrict__ bhhu)
{
    extern __shared__ __half smh[];
    const int tid = threadIdx.x, lane = tid & 31, wid = tid >> 5;
    const int wm = wid & 1, wn = wid >> 1, g = lane >> 2, tig = lane & 3;
    const int x = blockIdx.x;

    if (x >= 64) {
        projq_tile(smh, projBase + (x - 64), xT, wihr, wihu, xg_r, xg_u,
                   bihr, bhhr, bihu, bhhu, tid, wm, wn, g, tig);
        return;
    }

    const int m0 = (x >> 5) * 128, n0 = (x & 31) * 128;

    float acc[4][4][4];
#pragma unroll
    for (int a = 0; a < 4; a++)
#pragma unroll
        for (int b = 0; b < 4; b++)
#pragma unroll
            for (int c = 0; c < 4; c++) acc[a][b][c] = 0.f;

    if (!zeroInit)
        run_mainloop(smh, Hin + (size_t)(m0 >> 7) * 32 * 4096,
                     Whh + (size_t)(n0 >> 7) * 32 * 4096, acc, tid, wm, wn, g, tig);

    lstm_epilogue(acc, smh, xg, Cin, Cout, Hout, Hout /*unused hn*/,
                  m0, n0, /*final_t=*/-1, zeroInit, tid, wm, wn, g, tig);
}

// ---------------- classifier tile (device fn) -------------------------------
__device__ __forceinline__ void cls_tile(
    __half* smh, const __half* __restrict__ hn, const __half* __restrict__ wc,
    const float* __restrict__ bc, float* __restrict__ out,
    int m0, int n0, int tid, int wm, int wn, int g, int tig)
{
    float* biasS = (float*)(smh + EPI_OFF);
    if (tid < 128) {
        int np = n0 + tid;
        biasS[tid] = (np < C_) ? bc[np] : 0.f;
    }
    float acc[4][4][4];
#pragma unroll
    for (int a = 0; a < 4; a++)
#pragma unroll
        for (int b = 0; b < 4; b++)
#pragma unroll
            for (int c = 0; c < 4; c++) acc[a][b][c] = 0.f;

    run_mainloop(smh, hn + (size_t)(m0 >> 7) * 32 * 4096,
                 wc + (size_t)(n0 >> 7) * 32 * 4096, acc, tid, wm, wn, g, tig);

#pragma unroll
    for (int mi = 0; mi < 4; mi++) {
        const int R0 = m0 + wm * 64 + mi * 16;
#pragma unroll
        for (int ni = 0; ni < 4; ni++) {
            const int v = n0 + wn * 32 + ni * 8 + 2 * tig;
            const float bA0 = biasS[v - n0], bA1 = biasS[v - n0 + 1];
            const int r1 = R0 + g, r2 = R0 + g + 8;
            int or1 = (r1 & 255) * S_ + (r1 >> 8);
            int or2 = (r2 & 255) * S_ + (r2 >> 8);
            if (v < C_) {
                out[(size_t)or1 * C_ + v] = acc[mi][ni][0] + bA0;
                out[(size_t)or2 * C_ + v] = acc[mi][ni][2] + bA0;
            }
            if (v + 1 < C_) {
                out[(size_t)or1 * C_ + v + 1] = acc[mi][ni][1] + bA1;
                out[(size_t)or2 * C_ + v + 1] = acc[mi][ni][3] + bA1;
            }
        }
    }
}

// ---------------- fused unroll LSTM step + cls piggyback -------------------
__global__ void __launch_bounds__(256, 2) k_mma_lstm(
    const __half* __restrict__ Hin, const __half* __restrict__ Whh,
    const float* __restrict__ xg,
    const float* __restrict__ Cin, float* __restrict__ Cout,
    __half* __restrict__ Hout, __half* __restrict__ hn, int final_t,
    int nact2, int t_cls,
    const __half* __restrict__ wc, const float* __restrict__ bc,
    float* __restrict__ out)
{
    extern __shared__ __half smh[];
    const int tid = threadIdx.x, lane = tid & 31, wid = tid >> 5;
    const int wm = wid & 1, wn = wid >> 1, g = lane >> 2, tig = lane & 3;

    if ((int)blockIdx.y >= nact2) {
        if (blockIdx.x >= CLS_NB) return;
        int mb = t_cls * 2 + ((int)blockIdx.y - nact2);
        cls_tile(smh, hn, wc, bc, out, mb * 128, blockIdx.x * 128,
                 tid, wm, wn, g, tig);
        return;
    }

    const int m0 = blockIdx.y * 128, n0 = blockIdx.x * 128;

    float acc[4][4][4];
#pragma unroll
    for (int a = 0; a < 4; a++)
#pragma unroll
        for (int b = 0; b < 4; b++)
#pragma unroll
            for (int c = 0; c < 4; c++) acc[a][b][c] = 0.f;

    run_mainloop(smh, Hin + (size_t)(m0 >> 7) * 32 * 4096,
                 Whh + (size_t)(n0 >> 7) * 32 * 4096, acc, tid, wm, wn, g, tig);

    lstm_epilogue(acc, smh, xg, Cin, Cout, Hout, hn,
                  m0, n0, final_t, 0, tid, wm, wn, g, tig);
}

// ---------------- standalone classifier chunk (instance t) -----------------
__global__ void __launch_bounds__(256, 2) k_cls(
    const __half* __restrict__ hn, const __half* __restrict__ wc,
    const float* __restrict__ bc, float* __restrict__ out, int t)
{
    extern __shared__ __half smh[];
    const int tid = threadIdx.x, lane = tid & 31, wid = tid >> 5;
    const int wm = wid & 1, wn = wid >> 1, g = lane >> 2, tig = lane & 3;
    int mb = t * 2 + blockIdx.y;
    cls_tile(smh, hn, wc, bc, out, mb * 128, blockIdx.x * 128, tid, wm, wn, g, tig);
}

// ---------------- merged prep kernel (fp32 -> fp16, permute, TILE) ---------
#define PREP_XT   (SB * 32)
#define PREP_W    (G4 * 32)
#define PREP_WC   (WC_ROWS * 32)
#define PREP_TOT  (PREP_XT + 4 * PREP_W + PREP_WC)

__global__ void k_prep_all(
    const float* __restrict__ inp,
    const float* __restrict__ Whh_r, const float* __restrict__ Wih_r,
    const float* __restrict__ Wih_u, const float* __restrict__ Whh_u,
    const float* __restrict__ Wc,
    __half* __restrict__ xT, __half* __restrict__ whhr, __half* __restrict__ wihr,
    __half* __restrict__ wihu, __half* __restrict__ whhu, __half* __restrict__ wc)
{
    int idx = blockIdx.x * blockDim.x + threadIdx.x;
    if (idx >= PREP_TOT) return;
    const float* src = nullptr;
    __half* dstbase;
    int r, b32;
    if (idx < PREP_XT) {
        r = idx >> 5; b32 = idx & 31;
        int b = r % B_, s = r / B_;
        src = inp + (size_t)(b * S_ + s) * 1024 + b32 * 32;
        dstbase = xT;
    } else {
        int t = idx - PREP_XT;
        int seg = t / PREP_W;
        if (seg < 4) {
            int u = t - seg * PREP_W;
            r = u >> 5; b32 = u & 31;
            int wr = ((r & 3) << 10) | (r >> 2);
            const float* W = (seg == 0) ? Whh_r : (seg == 1) ? Wih_r
                            : (seg == 2) ? Wih_u : Whh_u;
            src = W + (size_t)wr * 1024 + b32 * 32;
            dstbase = (seg == 0) ? whhr : (seg == 1) ? wihr
                    : (seg == 2) ? wihu : whhu;
        } else {
            int u = t - 4 * PREP_W;
            r = u >> 5; b32 = u & 31;
            src = (r < C_) ? (Wc + (size_t)r * 1024 + b32 * 32) : nullptr;
            dstbase = wc;
        }
    }
    __half h[32];
    if (src) {
        float v[32];
#pragma unroll
        for (int i = 0; i < 8; i++) *(float4*)&v[i * 4] = *(const float4*)(src + i * 4);
#pragma unroll
        for (int p = 0; p < 32; p++) h[p] = __float2half_rn(v[perm_l(p)]);
    } else {
#pragma unroll
        for (int p = 0; p < 32; p++) h[p] = __float2half_rn(0.f);
    }
    // tiled layout: block (r>>7, b32), within-block offset (r&127)*32
    uint4* dst = (uint4*)(dstbase + ((size_t)(r >> 7) * 32 + b32) * 4096 + (r & 127) * 32);
#pragma unroll
    for (int i = 0; i < 4; i++) dst[i] = ((const uint4*)h)[i];
}

// ---------------- host orchestration ----------------
extern "C" void kernel_launch(void* const* d_in, const int* in_sizes, int n_in,
                              void* d_out, int out_size) {
    (void)in_sizes; (void)n_in; (void)out_size;
    const float* inp   = (const float*)d_in[0];
    const float* Wih_r = (const float*)d_in[1];
    const float* Whh_r = (const float*)d_in[2];
    const float* bih_r = (const float*)d_in[3];
    const float* bhh_r = (const float*)d_in[4];
    const float* Wih_u = (const float*)d_in[5];
    const float* Whh_u = (const float*)d_in[6];
    const float* bih_u = (const float*)d_in[7];
    const float* bhh_u = (const float*)d_in[8];
    const float* Wc    = (const float*)d_in[9];
    const float* bc    = (const float*)d_in[10];
    float* out = (float*)d_out;

    __half *xT, *hu, *hn, *whhr, *wihr, *wihu, *whhu, *wc;
    float *xg_r, *xg_u, *cu;
    cudaGetSymbolAddress((void**)&xT,   g_xT);
    cudaGetSymbolAddress((void**)&xg_r, g_xg_r);
    cudaGetSymbolAddress((void**)&xg_u, g_xg_u);
    cudaGetSymbolAddress((void**)&hu,   g_hu);
    cudaGetSymbolAddress((void**)&cu,   g_cu);
    cudaGetSymbolAddress((void**)&hn,   g_hn);
    cudaGetSymbolAddress((void**)&whhr, g_whhr);
    cudaGetSymbolAddress((void**)&wihr, g_wihr);
    cudaGetSymbolAddress((void**)&wihu, g_wihu);
    cudaGetSymbolAddress((void**)&whhu, g_whhu);
    cudaGetSymbolAddress((void**)&wc,   g_wc);
    __half* hu0 = hu;
    __half* hu1 = hu + (size_t)SB * 1024;

    cudaFuncSetAttribute(k_mma_lstm, cudaFuncAttributeMaxDynamicSharedMemorySize, SMEM_LSTM);
    cudaFuncSetAttribute(k_roll,     cudaFuncAttributeMaxDynamicSharedMemorySize, SMEM_LSTM);
    cudaFuncSetAttribute(k_projq,    cudaFuncAttributeMaxDynamicSharedMemorySize, SMEM_LIN);
    cudaFuncSetAttribute(k_cls,      cudaFuncAttributeMaxDynamicSharedMemorySize, SMEM_LIN);

    // 0) prep: all operands -> fp16, permuted, TILED (wc zero-padded)
    k_prep_all<<<(PREP_TOT + 255) / 256, 256>>>(inp, Whh_r, Wih_r, Wih_u, Whh_u, Wc,
                                                xT, whhr, wihr, wihu, whhu, wc);

    // 1) proj pre-launch (first 608 queue tiles)
    k_projq<<<PRELAUNCH, 256, SMEM_LIN>>>(xT, wihr, wihu, xg_r, xg_u,
                                          bih_r, bhh_r, bih_u, bhh_u);

    // 2) rolling LSTM: 14 steps, 64 LSTM tiles + 88 proj riders each
    for (int t = 0; t < S_; t++) {
        const __half* hin = hu0 + (size_t)(t - 1) * BH;   // unused when t==0
        const float*  cin = cu + (size_t)(t - 1) * BH;
        k_roll<<<64 + RIDE, 256, SMEM_LSTM>>>(
            (t == 0) ? hu0 : hin, whhr,
            xg_r + (size_t)t * B_ * G4,
            (t == 0) ? cu : cin, cu + (size_t)t * BH,
            hu0 + (size_t)t * BH,
            (t == 0) ? 1 : 0, PRELAUNCH + RIDE * t,
            xT, wihr, wihu, xg_r, xg_u, bih_r, bhh_r, bih_u, bhh_u);
    }

    // 3) unroll LSTM: 15 steps; steps j>=2 carry classifier chunk for t=15-j
    for (int j = 0; j <= S_; j++) {
        int nact = (15 - j < 14) ? (15 - j) : 14;
        const __half* hin = (j & 1) ? hu1 : hu0;
        __half*       ho  = (j & 1) ? hu0 : hu1;
        int final_t = S_ - j;
        int t_cls = (j >= 2) ? (15 - j) : -1;
        dim3 g(G4 / 128, nact * 2 + ((t_cls >= 0) ? 2 : 0));
        k_mma_lstm<<<g, 256, SMEM_LSTM>>>(hin, whhu, xg_u, cu, cu, ho, hn,
                                          final_t, nact * 2, t_cls,
                                          wc, bc, out);
    }

    // 4) final classifier chunk (instance t=0)
    {
        dim3 g(CLS_NB, 2);
        k_cls<<<g, 256, SMEM_LIN>>>(hn, wc, bc, out, 0);
    }
}